// round 2
// baseline (speedup 1.0000x reference)
#include <cuda_runtime.h>

// Fused 3-stage mode-contraction (Tucker transform) per batch element.
// Each stage: out[m*32 + i] = sum_c in[c*1024 + m] * w[c*32 + i]
// applied 3x (w0, w1, w2) on a 32x32x32 fp32 tile held entirely in smem.
// Round 2: inner product uses packed fma.rn.f32x2 (sm_100a FFMA2) to halve
// FMA instruction count; scalar FFMA issue rate was the measured bottleneck.

#define NTHREADS 512
#define TILE 32768            // 32*32*32 floats per batch element

typedef unsigned long long u64;

__device__ __forceinline__ void fma2(u64& d, u64 a, u64 b) {
    asm("fma.rn.f32x2 %0, %1, %2, %0;" : "+l"(d) : "l"(a), "l"(b));
}

__device__ __forceinline__ u64 pack2(float x) {
    u64 r;
    asm("mov.b64 %0, {%1, %1};" : "=l"(r) : "f"(x));
    return r;
}

__device__ __forceinline__ void unpack2(u64 v, float& lo, float& hi) {
    asm("mov.b64 {%0, %1}, %2;" : "=f"(lo), "=f"(hi) : "l"(v));
}

__global__ __launch_bounds__(NTHREADS, 1)
void tucker3_kernel(const float* __restrict__ x,
                    const float* __restrict__ w0,
                    const float* __restrict__ w1,
                    const float* __restrict__ w2,
                    float* __restrict__ out)
{
    extern __shared__ float smem[];
    float* S = smem;            // 32768 floats: data tile (in-place per stage)
    float* W = smem + TILE;     // 3 * 1024 floats: weights

    const int tid = threadIdx.x;
    const long base = (long)blockIdx.x * TILE;

    for (int i = tid; i < 1024; i += NTHREADS) {
        W[i]        = w0[i];
        W[1024 + i] = w1[i];
        W[2048 + i] = w2[i];
    }

    {
        const float4* xg = (const float4*)(x + base);
        float4* S4 = (float4*)S;
        #pragma unroll
        for (int i = 0; i < TILE / 4 / NTHREADS; i++)   // 16 iters
            S4[tid + i * NTHREADS] = xg[tid + i * NTHREADS];
    }
    __syncthreads();

    // Thread tile: 8 m-values x 8 i-values (as 8 x 4 f32x2 accumulators).
    const int warp  = tid >> 5;
    const int lane  = tid & 31;
    const int tm    = lane >> 2;            // 0..7
    const int ti    = lane & 3;             // 0..3
    const int mBase = warp * 64 + tm * 8;   // 8 consecutive m per thread
    const int iBase = ti * 8;               // 8 consecutive i per thread

    for (int s = 0; s < 3; s++) {
        const float* __restrict__ Wc = W + s * 1024;

        u64 acc[8][4];                      // [m][i-pair]; low lane = even i
        #pragma unroll
        for (int a = 0; a < 8; a++)
            #pragma unroll
            for (int q = 0; q < 4; q++)
                acc[a][q] = 0ull;

        #pragma unroll 2
        for (int c = 0; c < 32; c++) {
            float4 xa = *(const float4*)&S[c * 1024 + mBase];
            float4 xb = *(const float4*)&S[c * 1024 + mBase + 4];
            // weights as 4 packed f32x2 (memory order: low = even index)
            ulonglong2 wA = *(const ulonglong2*)&Wc[c * 32 + iBase];
            ulonglong2 wB = *(const ulonglong2*)&Wc[c * 32 + iBase + 4];
            u64 wq[4] = {wA.x, wA.y, wB.x, wB.y};

            float xs[8] = {xa.x, xa.y, xa.z, xa.w, xb.x, xb.y, xb.z, xb.w};

            #pragma unroll
            for (int a = 0; a < 8; a++) {
                u64 xd = pack2(xs[a]);
                #pragma unroll
                for (int q = 0; q < 4; q++)
                    fma2(acc[a][q], xd, wq[q]);
            }
        }

        __syncthreads();   // all reads of S for this stage are done

        // Write out[m*32 + i] back into S (transposed layout for next stage).
        #pragma unroll
        for (int a = 0; a < 8; a++) {
            const int m = mBase + a;
            float4 v0, v1;
            unpack2(acc[a][0], v0.x, v0.y);
            unpack2(acc[a][1], v0.z, v0.w);
            unpack2(acc[a][2], v1.x, v1.y);
            unpack2(acc[a][3], v1.z, v1.w);
            *(float4*)&S[m * 32 + iBase]     = v0;
            *(float4*)&S[m * 32 + iBase + 4] = v1;
        }
        __syncthreads();
    }

    {
        float4* og = (float4*)(out + base);
        const float4* S4 = (const float4*)S;
        #pragma unroll
        for (int i = 0; i < TILE / 4 / NTHREADS; i++)
            og[tid + i * NTHREADS] = S4[tid + i * NTHREADS];
    }
}

extern "C" void kernel_launch(void* const* d_in, const int* in_sizes, int n_in,
                              void* d_out, int out_size)
{
    const float* x  = (const float*)d_in[0];
    const float* w0 = (const float*)d_in[1];
    const float* w1 = (const float*)d_in[2];
    const float* w2 = (const float*)d_in[3];
    float* out = (float*)d_out;

    const int nBatch = in_sizes[0] >> 15;   // elements / 32768

    const size_t smemBytes = (TILE + 3 * 1024) * sizeof(float);  // 143360
    cudaFuncSetAttribute(tucker3_kernel,
                         cudaFuncAttributeMaxDynamicSharedMemorySize,
                         (int)smemBytes);

    tucker3_kernel<<<nBatch, NTHREADS, smemBytes>>>(x, w0, w1, w2, out);
}